// round 1
// baseline (speedup 1.0000x reference)
#include <cuda_runtime.h>

// Problem constants: B=4, C=256, H=W=64 -> N=4096 pixels
#define BATCH 4
#define CDIM 256
#define NPIX 4096

// Scratch (device globals: allocation-free per harness rules)
__device__ float g_Fq[(size_t)BATCH * CDIM * NPIX];
__device__ float g_G [(size_t)BATCH * CDIM * NPIX];
__device__ float g_Hv[(size_t)BATCH * CDIM * NPIX];
__device__ float g_R [(size_t)BATCH * CDIM * NPIX];
__device__ float g_S [(size_t)BATCH * NPIX * NPIX];   // 268 MB attention matrix

// ---------------------------------------------------------------------------
// Generic batched SGEMM: C[m,n] = sum_k A[m,k] * B[k,n] (+bias[m])
// Tile: BM=BN=128, BK=8, 256 threads, 8x8 microtile per thread.
// AKC=true  : A[m,k] = A[m*lda + k]   (k contiguous)
// AKC=false : A[m,k] = A[k*lda + m]   (m contiguous)
// Same convention for B with n <-> m roles: BKC=true : B[k,n] = B[n*ldb + k]
//                                           BKC=false: B[k,n] = B[k*ldb + n]
// All dims assumed multiples of tile sizes (true for this problem).
// ---------------------------------------------------------------------------
template <bool AKC, bool BKC>
__global__ void __launch_bounds__(256)
gemm128(const float* __restrict__ A, const float* __restrict__ Bm,
        float* __restrict__ Cm,
        int K, int lda, int ldb, int ldc,
        long long sA, long long sB, long long sC,
        const float* __restrict__ bias)
{
    A  += (long long)blockIdx.z * sA;
    Bm += (long long)blockIdx.z * sB;
    Cm += (long long)blockIdx.z * sC;

    const int m0 = blockIdx.y * 128;
    const int n0 = blockIdx.x * 128;
    const int tid = threadIdx.x;
    const int tx = tid & 15;       // 0..15 -> n microtile
    const int ty = tid >> 4;       // 0..15 -> m microtile

    // +4 pad: conflict-free scatter stores AND keeps float4 alignment (132 % 4 == 0)
    __shared__ float As[8][132];
    __shared__ float Bs[8][132];

    float acc[8][8];
#pragma unroll
    for (int i = 0; i < 8; i++)
#pragma unroll
        for (int j = 0; j < 8; j++) acc[i][j] = 0.f;

    auto loadA = [&](int kk) -> float4 {
        if constexpr (AKC) {
            // thread: m = tid/2, k-half = (tid&1)*4
            return *(const float4*)&A[(size_t)(m0 + (tid >> 1)) * lda + kk + ((tid & 1) << 2)];
        } else {
            // warp w loads k-row w, 32 float4 across m
            return *(const float4*)&A[(size_t)(kk + (tid >> 5)) * lda + m0 + ((tid & 31) << 2)];
        }
    };
    auto loadB = [&](int kk) -> float4 {
        if constexpr (BKC) {
            return *(const float4*)&Bm[(size_t)(n0 + (tid >> 1)) * ldb + kk + ((tid & 1) << 2)];
        } else {
            return *(const float4*)&Bm[(size_t)(kk + (tid >> 5)) * ldb + n0 + ((tid & 31) << 2)];
        }
    };

    float4 ar = loadA(0);
    float4 br = loadB(0);

    for (int k0 = 0; k0 < K; k0 += 8) {
        // store staged tile to smem
        if constexpr (AKC) {
            const int am = tid >> 1, ak = (tid & 1) << 2;
            As[ak + 0][am] = ar.x; As[ak + 1][am] = ar.y;
            As[ak + 2][am] = ar.z; As[ak + 3][am] = ar.w;
        } else {
            *(float4*)&As[tid >> 5][(tid & 31) << 2] = ar;
        }
        if constexpr (BKC) {
            const int bn = tid >> 1, bk = (tid & 1) << 2;
            Bs[bk + 0][bn] = br.x; Bs[bk + 1][bn] = br.y;
            Bs[bk + 2][bn] = br.z; Bs[bk + 3][bn] = br.w;
        } else {
            *(float4*)&Bs[tid >> 5][(tid & 31) << 2] = br;
        }
        __syncthreads();

        // prefetch next tile (overlaps with FFMA block below)
        if (k0 + 8 < K) {
            ar = loadA(k0 + 8);
            br = loadB(k0 + 8);
        }

#pragma unroll
        for (int k = 0; k < 8; k++) {
            float4 a0 = *(const float4*)&As[k][ty * 8];
            float4 a1 = *(const float4*)&As[k][ty * 8 + 4];
            float4 b0 = *(const float4*)&Bs[k][tx * 8];
            float4 b1 = *(const float4*)&Bs[k][tx * 8 + 4];
            float av[8] = {a0.x, a0.y, a0.z, a0.w, a1.x, a1.y, a1.z, a1.w};
            float bv[8] = {b0.x, b0.y, b0.z, b0.w, b1.x, b1.y, b1.z, b1.w};
#pragma unroll
            for (int i = 0; i < 8; i++)
#pragma unroll
                for (int j = 0; j < 8; j++)
                    acc[i][j] += av[i] * bv[j];
        }
        __syncthreads();
    }

    // epilogue
    float bv[8];
#pragma unroll
    for (int i = 0; i < 8; i++)
        bv[i] = bias ? bias[m0 + ty * 8 + i] : 0.f;

#pragma unroll
    for (int i = 0; i < 8; i++) {
        const size_t base = (size_t)(m0 + ty * 8 + i) * ldc + n0 + tx * 8;
        float4 v0 = {acc[i][0] + bv[i], acc[i][1] + bv[i], acc[i][2] + bv[i], acc[i][3] + bv[i]};
        float4 v1 = {acc[i][4] + bv[i], acc[i][5] + bv[i], acc[i][6] + bv[i], acc[i][7] + bv[i]};
        *(float4*)&Cm[base]     = v0;
        *(float4*)&Cm[base + 4] = v1;
    }
}

// ---------------------------------------------------------------------------
// Row softmax over 4096-wide rows, one block (256 thr) per row.
// ---------------------------------------------------------------------------
__global__ void __launch_bounds__(256) softmax_rows(float* __restrict__ S)
{
    float* row = S + (size_t)blockIdx.x * NPIX;
    const int tid = threadIdx.x;

    float v[16];
    float mx = -3.0e38f;
#pragma unroll
    for (int u = 0; u < 16; u++) {
        v[u] = row[tid + u * 256];
        mx = fmaxf(mx, v[u]);
    }

    __shared__ float sw[8];
#pragma unroll
    for (int o = 16; o; o >>= 1) mx = fmaxf(mx, __shfl_xor_sync(0xffffffffu, mx, o));
    if ((tid & 31) == 0) sw[tid >> 5] = mx;
    __syncthreads();
    float m0 = sw[0];
#pragma unroll
    for (int w = 1; w < 8; w++) m0 = fmaxf(m0, sw[w]);

    float s = 0.f;
#pragma unroll
    for (int u = 0; u < 16; u++) {
        v[u] = __expf(v[u] - m0);
        s += v[u];
    }
#pragma unroll
    for (int o = 16; o; o >>= 1) s += __shfl_xor_sync(0xffffffffu, s, o);
    __syncthreads();               // protect sw reuse
    if ((tid & 31) == 0) sw[tid >> 5] = s;
    __syncthreads();
    float tot = 0.f;
#pragma unroll
    for (int w = 0; w < 8; w++) tot += sw[w];

    const float inv = 1.0f / tot;
#pragma unroll
    for (int u = 0; u < 16; u++)
        row[tid + u * 256] = v[u] * inv;
}

// ---------------------------------------------------------------------------
// Launch. Inputs (metadata order): F_c, F_s, w_f, b_f, w_g, b_g, w_h, b_h, w_o, b_o
// ---------------------------------------------------------------------------
extern "C" void kernel_launch(void* const* d_in, const int* in_sizes, int n_in,
                              void* d_out, int out_size)
{
    const float* F_c = (const float*)d_in[0];
    const float* F_s = (const float*)d_in[1];
    const float* w_f = (const float*)d_in[2];
    const float* b_f = (const float*)d_in[3];
    const float* w_g = (const float*)d_in[4];
    const float* b_g = (const float*)d_in[5];
    const float* w_h = (const float*)d_in[6];
    const float* b_h = (const float*)d_in[7];
    const float* w_o = (const float*)d_in[8];
    const float* b_o = (const float*)d_in[9];
    float* out = (float*)d_out;

    float *Fq, *G, *Hv, *R, *S;
    cudaGetSymbolAddress((void**)&Fq, g_Fq);
    cudaGetSymbolAddress((void**)&G,  g_G);
    cudaGetSymbolAddress((void**)&Hv, g_Hv);
    cudaGetSymbolAddress((void**)&R,  g_R);
    cudaGetSymbolAddress((void**)&S,  g_S);

    const long long sCN = (long long)CDIM * NPIX;      // 1,048,576
    const long long sNN = (long long)NPIX * NPIX;      // 16,777,216

    dim3 gridConv(NPIX / 128, CDIM / 128, BATCH);      // 32 x 2 x 4
    dim3 gridS(NPIX / 128, NPIX / 128, BATCH);         // 32 x 32 x 4

    // 1) Fq = w_f @ F_c + b_f ; G = w_g @ F_s + b_g ; Hv = w_h @ F_s + b_h
    gemm128<true, false><<<gridConv, 256>>>(w_f, F_c, Fq, CDIM, CDIM, NPIX, NPIX, 0, sCN, sCN, b_f);
    gemm128<true, false><<<gridConv, 256>>>(w_g, F_s, G,  CDIM, CDIM, NPIX, NPIX, 0, sCN, sCN, b_g);
    gemm128<true, false><<<gridConv, 256>>>(w_h, F_s, Hv, CDIM, CDIM, NPIX, NPIX, 0, sCN, sCN, b_h);

    // 2) S[b,i,j] = sum_c Fq[b,c,i] * G[b,c,j]   (both k-strided)
    gemm128<false, false><<<gridS, 256>>>(Fq, G, S, CDIM, NPIX, NPIX, NPIX, sCN, sCN, sNN, nullptr);

    // 3) softmax over j
    softmax_rows<<<BATCH * NPIX, 256>>>(S);

    // 4) R[b,c,i] = sum_j Hv[b,c,j] * S[b,i,j]   (A k-contig, B k-contig)
    gemm128<true, true><<<gridConv, 256>>>(Hv, S, R, NPIX, NPIX, NPIX, NPIX, sCN, sNN, sCN, nullptr);

    // 5) out = w_o @ R + b_o
    gemm128<true, false><<<gridConv, 256>>>(w_o, R, out, CDIM, CDIM, NPIX, NPIX, 0, sCN, sCN, b_o);
}

// round 3
// speedup vs baseline: 1.8348x; 1.8348x over previous
#include <cuda_runtime.h>
#include <cuda_bf16.h>
#include <cstdint>

#define BATCH 4
#define CDIM  256
#define NPIX  4096
typedef __nv_bfloat16 bf16;

#define CN ((size_t)BATCH * NPIX * CDIM)      // 4,194,304
#define NN ((size_t)BATCH * NPIX * NPIX)      // 67,108,864

// ---------------------------------------------------------------------------
// Device scratch
// ---------------------------------------------------------------------------
__device__ bf16  g_FcT_h[CN], g_FcT_l[CN];    // F_c transposed [b][p][c]
__device__ bf16  g_FsT_h[CN], g_FsT_l[CN];
__device__ bf16  g_wf_h[CDIM*CDIM], g_wf_l[CDIM*CDIM];
__device__ bf16  g_wg_h[CDIM*CDIM], g_wg_l[CDIM*CDIM];
__device__ bf16  g_wh_h[CDIM*CDIM], g_wh_l[CDIM*CDIM];
__device__ bf16  g_wo_h[CDIM*CDIM], g_wo_l[CDIM*CDIM];
__device__ bf16  g_Fq_h[CN], g_Fq_l[CN];      // [b][i][c]
__device__ bf16  g_G_h [CN], g_G_l [CN];      // [b][j][c]
__device__ bf16  g_Hv_h[CN], g_Hv_l[CN];      // [b][c][j]
__device__ bf16  g_R_h [CN], g_R_l [CN];      // [b][i][c]
__device__ float g_S[NN];
__device__ bf16  g_Sh[NN], g_Sl[NN];

// ---------------------------------------------------------------------------
// PTX helpers (sm_80-level only: cp.async, ldmatrix, mma.sync)
// ---------------------------------------------------------------------------
__device__ __forceinline__ uint32_t smem_u32(const void* p) {
    uint32_t a;
    asm("{ .reg .u64 t; cvta.to.shared.u64 t, %1; cvt.u32.u64 %0, t; }" : "=r"(a) : "l"(p));
    return a;
}
#define CPA(s, g) asm volatile("cp.async.cg.shared.global [%0], [%1], 16;" :: "r"(s), "l"(g) : "memory")
#define CPC()     asm volatile("cp.async.commit_group;" ::: "memory")
#define CPW(n)    asm volatile("cp.async.wait_group %0;" :: "n"(n) : "memory")

__device__ __forceinline__ void ldsm4(uint32_t* r, uint32_t a) {
    asm volatile("ldmatrix.sync.aligned.m8n8.x4.shared.b16 {%0,%1,%2,%3}, [%4];"
        : "=r"(r[0]), "=r"(r[1]), "=r"(r[2]), "=r"(r[3]) : "r"(a));
}
__device__ __forceinline__ void ldsm2(uint32_t* r, uint32_t a) {
    asm volatile("ldmatrix.sync.aligned.m8n8.x2.shared.b16 {%0,%1}, [%2];"
        : "=r"(r[0]), "=r"(r[1]) : "r"(a));
}
__device__ __forceinline__ void mma_bf16(float* c, const uint32_t* a, const uint32_t* b) {
    asm volatile("mma.sync.aligned.m16n8k16.row.col.f32.bf16.bf16.f32 "
        "{%0,%1,%2,%3}, {%4,%5,%6,%7}, {%8,%9}, {%0,%1,%2,%3};"
        : "+f"(c[0]), "+f"(c[1]), "+f"(c[2]), "+f"(c[3])
        : "r"(a[0]), "r"(a[1]), "r"(a[2]), "r"(a[3]), "r"(b[0]), "r"(b[1]));
}
__device__ __forceinline__ void split2(float x, bf16& h, bf16& l) {
    h = __float2bfloat16(x);
    l = __float2bfloat16(x - __bfloat162float(h));
}

// ---------------------------------------------------------------------------
// GEMM: D[m,n] = sum_k A[m,k]*B[n,k], both operands K-contiguous bf16 hi/lo.
// CTA 128x128, BK=32, 3-stage cp.async pipeline, 8 warps (warp tile 64x32).
// 3-pass split accumulates into one fp32 accumulator.
// EPI: 0 = fp32 out [m][n] (+bias), 1 = bf16 split [m][n] (+bias),
//      2 = bf16 split transposed [n][m] (+bias on m)
// ---------------------------------------------------------------------------
#define RSB      80
#define TILE_SB  (128 * RSB)     // 10240
#define STAGE_SB (4 * TILE_SB)   // 40960
#define STAGES   3
#define DSMEM    (STAGES * STAGE_SB)  // 122880

template <int EPI>
__global__ void __launch_bounds__(256)
mma_gemm(const bf16* __restrict__ Ah_, const bf16* __restrict__ Al_,
         const bf16* __restrict__ Bh_, const bf16* __restrict__ Bl_,
         int K, int lda, int ldb, int ldo,
         long long sA, long long sB, long long sO,
         const float* __restrict__ bias,
         float* __restrict__ outF, bf16* __restrict__ oH, bf16* __restrict__ oL)
{
    extern __shared__ char smem[];
    const uint32_t sb = smem_u32(smem);
    const int tid = threadIdx.x;
    const int lane = tid & 31, wid = tid >> 5;
    const int wm = wid >> 2, wn = wid & 3;        // 2 x 4 warp grid
    const int z = blockIdx.z;
    const int m0 = blockIdx.y * 128, n0 = blockIdx.x * 128;

    const bf16* pT[4] = {Ah_ + (size_t)z * sA, Al_ + (size_t)z * sA,
                         Bh_ + (size_t)z * sB, Bl_ + (size_t)z * sB};
    const int nk = K / 32;

    const int r0 = tid >> 2, c0 = tid & 3;        // 16B chunk coords (rows 0..63)
    const int r1 = r0 + 64;                       // rows 64..127

    auto issue = [&](int kc) {
        if (kc >= nk) return;
        const uint32_t s0 = sb + (kc % STAGES) * STAGE_SB;
#pragma unroll
        for (int t = 0; t < 4; ++t) {
            const int ld = (t < 2) ? lda : ldb;
            const int base = (t < 2) ? m0 : n0;
            const bf16* g0 = pT[t] + (size_t)(base + r0) * ld + kc * 32 + c0 * 8;
            const bf16* g1 = pT[t] + (size_t)(base + r1) * ld + kc * 32 + c0 * 8;
            CPA(s0 + t * TILE_SB + r0 * RSB + c0 * 16, g0);
            CPA(s0 + t * TILE_SB + r1 * RSB + c0 * 16, g1);
        }
    };

    float acc[4][4][4];
#pragma unroll
    for (int i = 0; i < 4; ++i)
#pragma unroll
        for (int j = 0; j < 4; ++j)
#pragma unroll
            for (int q = 0; q < 4; ++q) acc[i][j][q] = 0.f;

    issue(0); CPC();
    issue(1); CPC();

    // ldmatrix lane offsets
    const int aRow = lane & 15;               // + wm*64 + i*16
    const int aKB  = (lane >> 4) * 16;        // byte offset for k-half
    const int bRow = lane & 7;                // + wn*32 + j*8
    const int bKB  = ((lane >> 3) & 1) * 16;

    for (int kc = 0; kc < nk; ++kc) {
        issue(kc + 2); CPC();
        CPW(2);
        __syncthreads();
        const uint32_t s0 = sb + (kc % STAGES) * STAGE_SB;
        const uint32_t aH = s0, aL = s0 + TILE_SB;
        const uint32_t bH = s0 + 2 * TILE_SB, bL = s0 + 3 * TILE_SB;
#pragma unroll
        for (int ks = 0; ks < 2; ++ks) {
            uint32_t Af[2][4][4];
#pragma unroll
            for (int i = 0; i < 4; ++i) {
                const uint32_t off = (uint32_t)(wm * 64 + i * 16 + aRow) * RSB + ks * 32 + aKB;
                ldsm4(Af[0][i], aH + off);
                ldsm4(Af[1][i], aL + off);
            }
#pragma unroll
            for (int j = 0; j < 4; ++j) {
                uint32_t Bf[2][2];
                const uint32_t off = (uint32_t)(wn * 32 + j * 8 + bRow) * RSB + ks * 32 + bKB;
                ldsm2(Bf[0], bH + off);
                ldsm2(Bf[1], bL + off);
#pragma unroll
                for (int i = 0; i < 4; ++i) {
                    mma_bf16(acc[i][j], Af[0][i], Bf[0]);   // hi*hi
                    mma_bf16(acc[i][j], Af[0][i], Bf[1]);   // hi*lo
                    mma_bf16(acc[i][j], Af[1][i], Bf[0]);   // lo*hi
                }
            }
        }
        __syncthreads();
    }

    // ---- epilogue: stage D (+bias on m) through smem ----
    float* stg = (float*)smem;                   // [128][132]
    const int gid = lane >> 2, tig = lane & 3;
#pragma unroll
    for (int i = 0; i < 4; ++i) {
        const int ml = wm * 64 + i * 16 + gid;
        const float bv0 = bias ? bias[m0 + ml] : 0.f;
        const float bv8 = bias ? bias[m0 + ml + 8] : 0.f;
#pragma unroll
        for (int j = 0; j < 4; ++j) {
            const int nl = wn * 32 + j * 8 + tig * 2;
            stg[ml * 132 + nl]           = acc[i][j][0] + bv0;
            stg[ml * 132 + nl + 1]       = acc[i][j][1] + bv0;
            stg[(ml + 8) * 132 + nl]     = acc[i][j][2] + bv8;
            stg[(ml + 8) * 132 + nl + 1] = acc[i][j][3] + bv8;
        }
    }
    __syncthreads();

    const int row = tid >> 1, half = tid & 1;
    if (EPI == 0) {
        float* dst = outF + (size_t)z * sO + (size_t)(m0 + row) * ldo + n0 + half * 64;
        const float4* s4 = (const float4*)&stg[row * 132 + half * 64];
#pragma unroll
        for (int i = 0; i < 16; ++i) ((float4*)dst)[i] = s4[i];
    } else if (EPI == 1) {
        const size_t base = (size_t)z * sO + (size_t)(m0 + row) * ldo + n0 + half * 64;
#pragma unroll
        for (int v = 0; v < 8; ++v) {
            uint32_t hw[4], lw[4];
#pragma unroll
            for (int q = 0; q < 4; ++q) {
                float x0 = stg[row * 132 + half * 64 + v * 8 + q * 2];
                float x1 = stg[row * 132 + half * 64 + v * 8 + q * 2 + 1];
                bf16 h0, l0, h1, l1;
                split2(x0, h0, l0); split2(x1, h1, l1);
                __nv_bfloat162 hp(h0, h1), lp(l0, l1);
                hw[q] = *(uint32_t*)&hp; lw[q] = *(uint32_t*)&lp;
            }
            *(uint4*)(oH + base + v * 8) = make_uint4(hw[0], hw[1], hw[2], hw[3]);
            *(uint4*)(oL + base + v * 8) = make_uint4(lw[0], lw[1], lw[2], lw[3]);
        }
    } else {
        const int n = row, mh = half * 64;
        const size_t base = (size_t)z * sO + (size_t)(n0 + n) * ldo + m0 + mh;
#pragma unroll
        for (int v = 0; v < 8; ++v) {
            uint32_t hw[4], lw[4];
#pragma unroll
            for (int q = 0; q < 4; ++q) {
                float x0 = stg[(mh + v * 8 + q * 2) * 132 + n];
                float x1 = stg[(mh + v * 8 + q * 2 + 1) * 132 + n];
                bf16 h0, l0, h1, l1;
                split2(x0, h0, l0); split2(x1, h1, l1);
                __nv_bfloat162 hp(h0, h1), lp(l0, l1);
                hw[q] = *(uint32_t*)&hp; lw[q] = *(uint32_t*)&lp;
            }
            *(uint4*)(oH + base + v * 8) = make_uint4(hw[0], hw[1], hw[2], hw[3]);
            *(uint4*)(oL + base + v * 8) = make_uint4(lw[0], lw[1], lw[2], lw[3]);
        }
    }
}

// ---------------------------------------------------------------------------
// fp32 [b][c][p] -> bf16 hi/lo transposed [b][p][c]
// ---------------------------------------------------------------------------
__global__ void __launch_bounds__(256)
tsplit(const float* __restrict__ X, bf16* __restrict__ oh, bf16* __restrict__ ol)
{
    __shared__ float t[32][33];
    const int b = blockIdx.z;
    const int pb = blockIdx.x * 32, cb = blockIdx.y * 32;
    const float* src = X + (size_t)b * CDIM * NPIX;
#pragma unroll
    for (int j = 0; j < 4; ++j) {
        int c = cb + threadIdx.y + j * 8;
        t[threadIdx.y + j * 8][threadIdx.x] = src[(size_t)c * NPIX + pb + threadIdx.x];
    }
    __syncthreads();
#pragma unroll
    for (int j = 0; j < 4; ++j) {
        int p = pb + threadIdx.y + j * 8;
        float v = t[threadIdx.x][threadIdx.y + j * 8];
        size_t o = (size_t)b * NPIX * CDIM + (size_t)p * CDIM + cb + threadIdx.x;
        bf16 h, l; split2(v, h, l);
        oh[o] = h; ol[o] = l;
    }
}

__global__ void __launch_bounds__(256)
wsplit(const float* __restrict__ w, bf16* __restrict__ h, bf16* __restrict__ l)
{
    int i = blockIdx.x * 256 + threadIdx.x;
    if (i < CDIM * CDIM) { bf16 a, b; split2(w[i], a, b); h[i] = a; l[i] = b; }
}

// ---------------------------------------------------------------------------
// Row softmax (4096 wide) -> bf16 hi/lo split
// ---------------------------------------------------------------------------
__global__ void __launch_bounds__(256)
softmax_split(const float* __restrict__ S, bf16* __restrict__ oh, bf16* __restrict__ ol)
{
    const float* rowp = S + (size_t)blockIdx.x * NPIX;
    const size_t ob = (size_t)blockIdx.x * NPIX;
    const int tid = threadIdx.x;

    float v[16];
    float mx = -3.0e38f;
#pragma unroll
    for (int u = 0; u < 16; ++u) { v[u] = rowp[tid + u * 256]; mx = fmaxf(mx, v[u]); }

    __shared__ float sw[8];
#pragma unroll
    for (int o = 16; o; o >>= 1) mx = fmaxf(mx, __shfl_xor_sync(0xffffffffu, mx, o));
    if ((tid & 31) == 0) sw[tid >> 5] = mx;
    __syncthreads();
    float m0 = sw[0];
#pragma unroll
    for (int w = 1; w < 8; ++w) m0 = fmaxf(m0, sw[w]);

    float s = 0.f;
#pragma unroll
    for (int u = 0; u < 16; ++u) { v[u] = __expf(v[u] - m0); s += v[u]; }
#pragma unroll
    for (int o = 16; o; o >>= 1) s += __shfl_xor_sync(0xffffffffu, s, o);
    __syncthreads();
    if ((tid & 31) == 0) sw[tid >> 5] = s;
    __syncthreads();
    float tot = 0.f;
#pragma unroll
    for (int w = 0; w < 8; ++w) tot += sw[w];

    const float inv = 1.0f / tot;
#pragma unroll
    for (int u = 0; u < 16; ++u) {
        bf16 h, l; split2(v[u] * inv, h, l);
        oh[ob + tid + u * 256] = h;
        ol[ob + tid + u * 256] = l;
    }
}

// ---------------------------------------------------------------------------
// Launch
// ---------------------------------------------------------------------------
extern "C" void kernel_launch(void* const* d_in, const int* in_sizes, int n_in,
                              void* d_out, int out_size)
{
    const float* F_c = (const float*)d_in[0];
    const float* F_s = (const float*)d_in[1];
    const float* w_f = (const float*)d_in[2];
    const float* b_f = (const float*)d_in[3];
    const float* w_g = (const float*)d_in[4];
    const float* b_g = (const float*)d_in[5];
    const float* w_h = (const float*)d_in[6];
    const float* b_h = (const float*)d_in[7];
    const float* w_o = (const float*)d_in[8];
    const float* b_o = (const float*)d_in[9];
    float* out = (float*)d_out;

    bf16 *FcTh, *FcTl, *FsTh, *FsTl, *wfh, *wfl, *wgh, *wgl, *whh, *whl, *woh, *wol;
    bf16 *Fqh, *Fql, *Gh, *Gl, *Hvh, *Hvl, *Rh, *Rl, *Sh, *Sl;
    float* S;
    cudaGetSymbolAddress((void**)&FcTh, g_FcT_h); cudaGetSymbolAddress((void**)&FcTl, g_FcT_l);
    cudaGetSymbolAddress((void**)&FsTh, g_FsT_h); cudaGetSymbolAddress((void**)&FsTl, g_FsT_l);
    cudaGetSymbolAddress((void**)&wfh, g_wf_h);   cudaGetSymbolAddress((void**)&wfl, g_wf_l);
    cudaGetSymbolAddress((void**)&wgh, g_wg_h);   cudaGetSymbolAddress((void**)&wgl, g_wg_l);
    cudaGetSymbolAddress((void**)&whh, g_wh_h);   cudaGetSymbolAddress((void**)&whl, g_wh_l);
    cudaGetSymbolAddress((void**)&woh, g_wo_h);   cudaGetSymbolAddress((void**)&wol, g_wo_l);
    cudaGetSymbolAddress((void**)&Fqh, g_Fq_h);   cudaGetSymbolAddress((void**)&Fql, g_Fq_l);
    cudaGetSymbolAddress((void**)&Gh,  g_G_h);    cudaGetSymbolAddress((void**)&Gl,  g_G_l);
    cudaGetSymbolAddress((void**)&Hvh, g_Hv_h);   cudaGetSymbolAddress((void**)&Hvl, g_Hv_l);
    cudaGetSymbolAddress((void**)&Rh,  g_R_h);    cudaGetSymbolAddress((void**)&Rl,  g_R_l);
    cudaGetSymbolAddress((void**)&S,   g_S);
    cudaGetSymbolAddress((void**)&Sh,  g_Sh);     cudaGetSymbolAddress((void**)&Sl,  g_Sl);

    cudaFuncSetAttribute(mma_gemm<0>, cudaFuncAttributeMaxDynamicSharedMemorySize, DSMEM);
    cudaFuncSetAttribute(mma_gemm<1>, cudaFuncAttributeMaxDynamicSharedMemorySize, DSMEM);
    cudaFuncSetAttribute(mma_gemm<2>, cudaFuncAttributeMaxDynamicSharedMemorySize, DSMEM);

    const long long cn = (long long)NPIX * CDIM;
    const long long nn = (long long)NPIX * NPIX;

    tsplit<<<dim3(128, 8, BATCH), dim3(32, 8)>>>(F_c, FcTh, FcTl);
    tsplit<<<dim3(128, 8, BATCH), dim3(32, 8)>>>(F_s, FsTh, FsTl);
    wsplit<<<256, 256>>>(w_f, wfh, wfl);
    wsplit<<<256, 256>>>(w_g, wgh, wgl);
    wsplit<<<256, 256>>>(w_h, whh, whl);
    wsplit<<<256, 256>>>(w_o, woh, wol);

    dim3 gConv(NPIX / 128, CDIM / 128, BATCH);   // 32 x 2 x 4
    dim3 gS(NPIX / 128, NPIX / 128, BATCH);      // 32 x 32 x 4

    // G1: Fq_t[i][c] = (w_f @ F_c + b_f)^T   (EPI 2)
    mma_gemm<2><<<gConv, 256, DSMEM>>>(wfh, wfl, FcTh, FcTl,
        CDIM, CDIM, CDIM, CDIM, 0, cn, cn, b_f, nullptr, Fqh, Fql);
    // G2: G_t[j][c]
    mma_gemm<2><<<gConv, 256, DSMEM>>>(wgh, wgl, FsTh, FsTl,
        CDIM, CDIM, CDIM, CDIM, 0, cn, cn, b_g, nullptr, Gh, Gl);
    // G3: Hv[c][j]   (EPI 1)
    mma_gemm<1><<<gConv, 256, DSMEM>>>(whh, whl, FsTh, FsTl,
        CDIM, CDIM, CDIM, NPIX, 0, cn, cn, b_h, nullptr, Hvh, Hvl);
    // G4: S[i][j] = Fq_t[i,:].G_t[j,:]   (EPI 0)
    mma_gemm<0><<<gS, 256, DSMEM>>>(Fqh, Fql, Gh, Gl,
        CDIM, CDIM, CDIM, NPIX, cn, cn, nn, nullptr, S, nullptr, nullptr);
    // softmax rows -> split
    softmax_split<<<BATCH * NPIX, 256>>>(S, Sh, Sl);
    // G5: R_t[i][c]: D[c][i] = sum_j Hv[c][j] * P[i][j]   (EPI 2)
    mma_gemm<2><<<gConv, 256, DSMEM>>>(Hvh, Hvl, Sh, Sl,
        NPIX, NPIX, NPIX, CDIM, cn, nn, cn, nullptr, nullptr, Rh, Rl);
    // G6: out = w_o @ R + b_o   (EPI 0)
    mma_gemm<0><<<gConv, 256, DSMEM>>>(woh, wol, Rh, Rl,
        CDIM, CDIM, CDIM, NPIX, 0, cn, cn, b_o, out, nullptr, nullptr);
}

// round 4
// speedup vs baseline: 2.1347x; 1.1635x over previous
#include <cuda_runtime.h>
#include <cuda_bf16.h>
#include <cstdint>

#define BATCH 4
#define CDIM  256
#define NPIX  4096
typedef __nv_bfloat16 bf16;

#define CN ((size_t)BATCH * NPIX * CDIM)      // 4,194,304
#define NN ((size_t)BATCH * NPIX * NPIX)      // 67,108,864

// ---------------------------------------------------------------------------
// Device scratch
// ---------------------------------------------------------------------------
__device__ bf16  g_FcT_h[CN], g_FcT_l[CN];    // F_c transposed [b][p][c]
__device__ bf16  g_FsT_h[CN], g_FsT_l[CN];
__device__ bf16  g_wf_h[CDIM*CDIM], g_wf_l[CDIM*CDIM];
__device__ bf16  g_wg_h[CDIM*CDIM], g_wg_l[CDIM*CDIM];
__device__ bf16  g_wh_h[CDIM*CDIM], g_wh_l[CDIM*CDIM];
__device__ bf16  g_wo_h[CDIM*CDIM], g_wo_l[CDIM*CDIM];
__device__ bf16  g_Fq_h[CN], g_Fq_l[CN];      // [b][i][c]
__device__ bf16  g_G_h [CN], g_G_l [CN];      // [b][j][c]
__device__ bf16  g_Hv_h[CN], g_Hv_l[CN];      // [b][c][j]
__device__ bf16  g_R_h [CN], g_R_l [CN];      // [b][i][c]
__device__ float g_S[NN];
__device__ bf16  g_Sh[NN], g_Sl[NN];

// ---------------------------------------------------------------------------
// PTX helpers (sm_80-level only)
// ---------------------------------------------------------------------------
__device__ __forceinline__ uint32_t smem_u32(const void* p) {
    uint32_t a;
    asm("{ .reg .u64 t; cvta.to.shared.u64 t, %1; cvt.u32.u64 %0, t; }" : "=r"(a) : "l"(p));
    return a;
}
#define CPA(s, g) asm volatile("cp.async.cg.shared.global [%0], [%1], 16;" :: "r"(s), "l"(g) : "memory")
#define CPC()     asm volatile("cp.async.commit_group;" ::: "memory")
#define CPW(n)    asm volatile("cp.async.wait_group %0;" :: "n"(n) : "memory")

__device__ __forceinline__ void ldsm4(uint32_t* r, uint32_t a) {
    asm volatile("ldmatrix.sync.aligned.m8n8.x4.shared.b16 {%0,%1,%2,%3}, [%4];"
        : "=r"(r[0]), "=r"(r[1]), "=r"(r[2]), "=r"(r[3]) : "r"(a));
}
__device__ __forceinline__ void ldsm2(uint32_t* r, uint32_t a) {
    asm volatile("ldmatrix.sync.aligned.m8n8.x2.shared.b16 {%0,%1}, [%2];"
        : "=r"(r[0]), "=r"(r[1]) : "r"(a));
}
__device__ __forceinline__ void mma_bf16(float* c, const uint32_t* a, const uint32_t* b) {
    asm volatile("mma.sync.aligned.m16n8k16.row.col.f32.bf16.bf16.f32 "
        "{%0,%1,%2,%3}, {%4,%5,%6,%7}, {%8,%9}, {%0,%1,%2,%3};"
        : "+f"(c[0]), "+f"(c[1]), "+f"(c[2]), "+f"(c[3])
        : "r"(a[0]), "r"(a[1]), "r"(a[2]), "r"(a[3]), "r"(b[0]), "r"(b[1]));
}
__device__ __forceinline__ void split2(float x, bf16& h, bf16& l) {
    h = __float2bfloat16(x);
    l = __float2bfloat16(x - __bfloat162float(h));
}

// ---------------------------------------------------------------------------
// GEMM: D[m,n] = sum_k A[m,k]*B[n,k]; operands K-contiguous bf16 hi/lo.
// CTA 128x128, BK=32, 2-stage cp.async pipeline, 8 warps (warp tile 64x32),
// 2 CTAs/SM. 3-pass split into one fp32 accumulator.
// EPI: 0 = fp32 [m][n] (+bias), 1 = bf16 split [m][n] (+bias),
//      2 = bf16 split transposed [n][m] (+bias on m)
// ---------------------------------------------------------------------------
#define RSB      80
#define TILE_SB  (128 * RSB)     // 10240
#define STAGE_SB (4 * TILE_SB)   // 40960
#define STAGES   2
#define DSMEM    (STAGES * STAGE_SB)  // 81920

template <int EPI>
__global__ void __launch_bounds__(256, 2)
mma_gemm(const bf16* __restrict__ Ah_, const bf16* __restrict__ Al_,
         const bf16* __restrict__ Bh_, const bf16* __restrict__ Bl_,
         int K, int lda, int ldb, int ldo,
         long long sA, long long sB, long long sO,
         const float* __restrict__ bias,
         float* __restrict__ outF, bf16* __restrict__ oH, bf16* __restrict__ oL)
{
    extern __shared__ char smem[];
    const uint32_t sb = smem_u32(smem);
    const int tid = threadIdx.x;
    const int lane = tid & 31, wid = tid >> 5;
    const int wm = wid >> 2, wn = wid & 3;        // 2 x 4 warp grid
    const int z = blockIdx.z;
    const int m0 = blockIdx.y * 128, n0 = blockIdx.x * 128;

    const bf16* pT[4] = {Ah_ + (size_t)z * sA, Al_ + (size_t)z * sA,
                         Bh_ + (size_t)z * sB, Bl_ + (size_t)z * sB};
    const int nk = K / 32;

    const int r0 = tid >> 2, c0 = tid & 3;        // 16B chunk coords (rows 0..63)
    const int r1 = r0 + 64;

    auto issue = [&](int kc) {
        if (kc >= nk) return;
        const uint32_t s0 = sb + (kc & 1) * STAGE_SB;
#pragma unroll
        for (int t = 0; t < 4; ++t) {
            const int ld = (t < 2) ? lda : ldb;
            const int base = (t < 2) ? m0 : n0;
            const bf16* g0 = pT[t] + (size_t)(base + r0) * ld + kc * 32 + c0 * 8;
            const bf16* g1 = pT[t] + (size_t)(base + r1) * ld + kc * 32 + c0 * 8;
            CPA(s0 + t * TILE_SB + r0 * RSB + c0 * 16, g0);
            CPA(s0 + t * TILE_SB + r1 * RSB + c0 * 16, g1);
        }
    };

    float acc[4][4][4];
#pragma unroll
    for (int i = 0; i < 4; ++i)
#pragma unroll
        for (int j = 0; j < 4; ++j)
#pragma unroll
            for (int q = 0; q < 4; ++q) acc[i][j][q] = 0.f;

    issue(0); CPC();
    issue(1); CPC();

    const int aRow = lane & 15;
    const int aKB  = (lane >> 4) * 16;
    const int bRow = lane & 7;
    const int bKB  = ((lane >> 3) & 1) * 16;

    for (int kc = 0; kc < nk; ++kc) {
        CPW(1);
        __syncthreads();
        const uint32_t s0 = sb + (kc & 1) * STAGE_SB;
        const uint32_t aH = s0, aL = s0 + TILE_SB;
        const uint32_t bH = s0 + 2 * TILE_SB, bL = s0 + 3 * TILE_SB;
#pragma unroll
        for (int ks = 0; ks < 2; ++ks) {
            uint32_t Af[2][4][4];
#pragma unroll
            for (int i = 0; i < 4; ++i) {
                const uint32_t off = (uint32_t)(wm * 64 + i * 16 + aRow) * RSB + ks * 32 + aKB;
                ldsm4(Af[0][i], aH + off);
                ldsm4(Af[1][i], aL + off);
            }
#pragma unroll
            for (int j = 0; j < 4; ++j) {
                uint32_t Bf[2][2];
                const uint32_t off = (uint32_t)(wn * 32 + j * 8 + bRow) * RSB + ks * 32 + bKB;
                ldsm2(Bf[0], bH + off);
                ldsm2(Bf[1], bL + off);
#pragma unroll
                for (int i = 0; i < 4; ++i) {
                    mma_bf16(acc[i][j], Af[0][i], Bf[0]);   // hi*hi
                    mma_bf16(acc[i][j], Af[0][i], Bf[1]);   // hi*lo
                    mma_bf16(acc[i][j], Af[1][i], Bf[0]);   // lo*hi
                }
            }
        }
        __syncthreads();
        issue(kc + 2); CPC();
    }

    // ---- epilogue: stage D (+bias on m) through smem ----
    float* stg = (float*)smem;                   // [128][132] = 67.6KB < 80KB
    const int gid = lane >> 2, tig = lane & 3;
#pragma unroll
    for (int i = 0; i < 4; ++i) {
        const int ml = wm * 64 + i * 16 + gid;
        const float bv0 = bias ? bias[m0 + ml] : 0.f;
        const float bv8 = bias ? bias[m0 + ml + 8] : 0.f;
#pragma unroll
        for (int j = 0; j < 4; ++j) {
            const int nl = wn * 32 + j * 8 + tig * 2;
            stg[ml * 132 + nl]           = acc[i][j][0] + bv0;
            stg[ml * 132 + nl + 1]       = acc[i][j][1] + bv0;
            stg[(ml + 8) * 132 + nl]     = acc[i][j][2] + bv8;
            stg[(ml + 8) * 132 + nl + 1] = acc[i][j][3] + bv8;
        }
    }
    __syncthreads();

    const int row = tid >> 1, half = tid & 1;
    if (EPI == 0) {
        float* dst = outF + (size_t)z * sO + (size_t)(m0 + row) * ldo + n0 + half * 64;
        const float4* s4 = (const float4*)&stg[row * 132 + half * 64];
#pragma unroll
        for (int i = 0; i < 16; ++i) ((float4*)dst)[i] = s4[i];
    } else if (EPI == 1) {
        const size_t base = (size_t)z * sO + (size_t)(m0 + row) * ldo + n0 + half * 64;
#pragma unroll
        for (int v = 0; v < 8; ++v) {
            uint32_t hw[4], lw[4];
#pragma unroll
            for (int q = 0; q < 4; ++q) {
                float x0 = stg[row * 132 + half * 64 + v * 8 + q * 2];
                float x1 = stg[row * 132 + half * 64 + v * 8 + q * 2 + 1];
                bf16 h0, l0, h1, l1;
                split2(x0, h0, l0); split2(x1, h1, l1);
                __nv_bfloat162 hp(h0, h1), lp(l0, l1);
                hw[q] = *(uint32_t*)&hp; lw[q] = *(uint32_t*)&lp;
            }
            *(uint4*)(oH + base + v * 8) = make_uint4(hw[0], hw[1], hw[2], hw[3]);
            *(uint4*)(oL + base + v * 8) = make_uint4(lw[0], lw[1], lw[2], lw[3]);
        }
    } else {
        const int n = row, mh = half * 64;
        const size_t base = (size_t)z * sO + (size_t)(n0 + n) * ldo + m0 + mh;
#pragma unroll
        for (int v = 0; v < 8; ++v) {
            uint32_t hw[4], lw[4];
#pragma unroll
            for (int q = 0; q < 4; ++q) {
                float x0 = stg[(mh + v * 8 + q * 2) * 132 + n];
                float x1 = stg[(mh + v * 8 + q * 2 + 1) * 132 + n];
                bf16 h0, l0, h1, l1;
                split2(x0, h0, l0); split2(x1, h1, l1);
                __nv_bfloat162 hp(h0, h1), lp(l0, l1);
                hw[q] = *(uint32_t*)&hp; lw[q] = *(uint32_t*)&lp;
            }
            *(uint4*)(oH + base + v * 8) = make_uint4(hw[0], hw[1], hw[2], hw[3]);
            *(uint4*)(oL + base + v * 8) = make_uint4(lw[0], lw[1], lw[2], lw[3]);
        }
    }
}

// ---------------------------------------------------------------------------
// fp32 [b][c][p] -> bf16 hi/lo transposed [b][p][c]
// ---------------------------------------------------------------------------
__global__ void __launch_bounds__(256)
tsplit(const float* __restrict__ X, bf16* __restrict__ oh, bf16* __restrict__ ol)
{
    __shared__ float t[32][33];
    const int b = blockIdx.z;
    const int pb = blockIdx.x * 32, cb = blockIdx.y * 32;
    const float* src = X + (size_t)b * CDIM * NPIX;
#pragma unroll
    for (int j = 0; j < 4; ++j) {
        int c = cb + threadIdx.y + j * 8;
        t[threadIdx.y + j * 8][threadIdx.x] = src[(size_t)c * NPIX + pb + threadIdx.x];
    }
    __syncthreads();
#pragma unroll
    for (int j = 0; j < 4; ++j) {
        int p = pb + threadIdx.y + j * 8;
        float v = t[threadIdx.x][threadIdx.y + j * 8];
        size_t o = (size_t)b * NPIX * CDIM + (size_t)p * CDIM + cb + threadIdx.x;
        bf16 h, l; split2(v, h, l);
        oh[o] = h; ol[o] = l;
    }
}

// All 4 weight matrices in one launch (grid.y selects matrix)
__global__ void __launch_bounds__(256)
wsplit_all(const float* __restrict__ w0, const float* __restrict__ w1,
           const float* __restrict__ w2, const float* __restrict__ w3,
           bf16* __restrict__ h0, bf16* __restrict__ l0,
           bf16* __restrict__ h1, bf16* __restrict__ l1,
           bf16* __restrict__ h2, bf16* __restrict__ l2,
           bf16* __restrict__ h3, bf16* __restrict__ l3)
{
    const float* w = (blockIdx.y == 0) ? w0 : (blockIdx.y == 1) ? w1 : (blockIdx.y == 2) ? w2 : w3;
    bf16* hh = (blockIdx.y == 0) ? h0 : (blockIdx.y == 1) ? h1 : (blockIdx.y == 2) ? h2 : h3;
    bf16* ll = (blockIdx.y == 0) ? l0 : (blockIdx.y == 1) ? l1 : (blockIdx.y == 2) ? l2 : l3;
    int i = blockIdx.x * 256 + threadIdx.x;
    if (i < CDIM * CDIM) { bf16 a, b; split2(w[i], a, b); hh[i] = a; ll[i] = b; }
}

// ---------------------------------------------------------------------------
// Row softmax (4096 wide) -> bf16 hi/lo split
// ---------------------------------------------------------------------------
__global__ void __launch_bounds__(256)
softmax_split(const float* __restrict__ S, bf16* __restrict__ oh, bf16* __restrict__ ol)
{
    const float* rowp = S + (size_t)blockIdx.x * NPIX;
    const size_t ob = (size_t)blockIdx.x * NPIX;
    const int tid = threadIdx.x;

    float v[16];
    float mx = -3.0e38f;
#pragma unroll
    for (int u = 0; u < 16; ++u) { v[u] = rowp[tid + u * 256]; mx = fmaxf(mx, v[u]); }

    __shared__ float sw[8];
#pragma unroll
    for (int o = 16; o; o >>= 1) mx = fmaxf(mx, __shfl_xor_sync(0xffffffffu, mx, o));
    if ((tid & 31) == 0) sw[tid >> 5] = mx;
    __syncthreads();
    float m0 = sw[0];
#pragma unroll
    for (int w = 1; w < 8; ++w) m0 = fmaxf(m0, sw[w]);

    float s = 0.f;
#pragma unroll
    for (int u = 0; u < 16; ++u) { v[u] = __expf(v[u] - m0); s += v[u]; }
#pragma unroll
    for (int o = 16; o; o >>= 1) s += __shfl_xor_sync(0xffffffffu, s, o);
    __syncthreads();
    if ((tid & 31) == 0) sw[tid >> 5] = s;
    __syncthreads();
    float tot = 0.f;
#pragma unroll
    for (int w = 0; w < 8; ++w) tot += sw[w];

    const float inv = 1.0f / tot;
#pragma unroll
    for (int u = 0; u < 16; ++u) {
        bf16 h, l; split2(v[u] * inv, h, l);
        oh[ob + tid + u * 256] = h;
        ol[ob + tid + u * 256] = l;
    }
}

// ---------------------------------------------------------------------------
// Launch — ordered so launch #6 (ncu -s 5 -c 1 target) is G4, the big GEMM.
// ---------------------------------------------------------------------------
extern "C" void kernel_launch(void* const* d_in, const int* in_sizes, int n_in,
                              void* d_out, int out_size)
{
    const float* F_c = (const float*)d_in[0];
    const float* F_s = (const float*)d_in[1];
    const float* w_f = (const float*)d_in[2];
    const float* b_f = (const float*)d_in[3];
    const float* w_g = (const float*)d_in[4];
    const float* b_g = (const float*)d_in[5];
    const float* w_h = (const float*)d_in[6];
    const float* b_h = (const float*)d_in[7];
    const float* w_o = (const float*)d_in[8];
    const float* b_o = (const float*)d_in[9];
    float* out = (float*)d_out;

    bf16 *FcTh, *FcTl, *FsTh, *FsTl, *wfh, *wfl, *wgh, *wgl, *whh, *whl, *woh, *wol;
    bf16 *Fqh, *Fql, *Gh, *Gl, *Hvh, *Hvl, *Rh, *Rl, *Sh, *Sl;
    float* S;
    cudaGetSymbolAddress((void**)&FcTh, g_FcT_h); cudaGetSymbolAddress((void**)&FcTl, g_FcT_l);
    cudaGetSymbolAddress((void**)&FsTh, g_FsT_h); cudaGetSymbolAddress((void**)&FsTl, g_FsT_l);
    cudaGetSymbolAddress((void**)&wfh, g_wf_h);   cudaGetSymbolAddress((void**)&wfl, g_wf_l);
    cudaGetSymbolAddress((void**)&wgh, g_wg_h);   cudaGetSymbolAddress((void**)&wgl, g_wg_l);
    cudaGetSymbolAddress((void**)&whh, g_wh_h);   cudaGetSymbolAddress((void**)&whl, g_wh_l);
    cudaGetSymbolAddress((void**)&woh, g_wo_h);   cudaGetSymbolAddress((void**)&wol, g_wo_l);
    cudaGetSymbolAddress((void**)&Fqh, g_Fq_h);   cudaGetSymbolAddress((void**)&Fql, g_Fq_l);
    cudaGetSymbolAddress((void**)&Gh,  g_G_h);    cudaGetSymbolAddress((void**)&Gl,  g_G_l);
    cudaGetSymbolAddress((void**)&Hvh, g_Hv_h);   cudaGetSymbolAddress((void**)&Hvl, g_Hv_l);
    cudaGetSymbolAddress((void**)&Rh,  g_R_h);    cudaGetSymbolAddress((void**)&Rl,  g_R_l);
    cudaGetSymbolAddress((void**)&S,   g_S);
    cudaGetSymbolAddress((void**)&Sh,  g_Sh);     cudaGetSymbolAddress((void**)&Sl,  g_Sl);

    cudaFuncSetAttribute(mma_gemm<0>, cudaFuncAttributeMaxDynamicSharedMemorySize, DSMEM);
    cudaFuncSetAttribute(mma_gemm<1>, cudaFuncAttributeMaxDynamicSharedMemorySize, DSMEM);
    cudaFuncSetAttribute(mma_gemm<2>, cudaFuncAttributeMaxDynamicSharedMemorySize, DSMEM);

    const long long cn = (long long)NPIX * CDIM;
    const long long nn = (long long)NPIX * NPIX;

    dim3 gConv(NPIX / 128, CDIM / 128, BATCH);   // 32 x 2 x 4
    dim3 gS(NPIX / 128, NPIX / 128, BATCH);      // 32 x 32 x 4

    // L1: all weight splits
    wsplit_all<<<dim3(256, 4), 256>>>(w_f, w_g, w_h, w_o,
        wfh, wfl, wgh, wgl, whh, whl, woh, wol);
    // L2, L3: input transposes
    tsplit<<<dim3(128, 8, BATCH), dim3(32, 8)>>>(F_c, FcTh, FcTl);
    tsplit<<<dim3(128, 8, BATCH), dim3(32, 8)>>>(F_s, FsTh, FsTl);
    // L4 (G1): Fq_t[i][c]
    mma_gemm<2><<<gConv, 256, DSMEM>>>(wfh, wfl, FcTh, FcTl,
        CDIM, CDIM, CDIM, CDIM, 0, cn, cn, b_f, nullptr, Fqh, Fql);
    // L5 (G2): G_t[j][c]
    mma_gemm<2><<<gConv, 256, DSMEM>>>(wgh, wgl, FsTh, FsTl,
        CDIM, CDIM, CDIM, CDIM, 0, cn, cn, b_g, nullptr, Gh, Gl);
    // L6 (G4): S[i][j] — ncu target
    mma_gemm<0><<<gS, 256, DSMEM>>>(Fqh, Fql, Gh, Gl,
        CDIM, CDIM, CDIM, NPIX, cn, cn, nn, nullptr, S, nullptr, nullptr);
    // L7 (G3): Hv[c][j]
    mma_gemm<1><<<gConv, 256, DSMEM>>>(whh, whl, FsTh, FsTl,
        CDIM, CDIM, CDIM, NPIX, 0, cn, cn, b_h, nullptr, Hvh, Hvl);
    // L8: softmax
    softmax_split<<<BATCH * NPIX, 256>>>(S, Sh, Sl);
    // L9 (G5): R_t[i][c]
    mma_gemm<2><<<gConv, 256, DSMEM>>>(Hvh, Hvl, Sh, Sl,
        NPIX, NPIX, NPIX, CDIM, cn, nn, cn, nullptr, nullptr, Rh, Rl);
    // L10 (G6): out = w_o @ R + b_o
    mma_gemm<0><<<gConv, 256, DSMEM>>>(woh, wol, Rh, Rl,
        CDIM, CDIM, CDIM, NPIX, 0, cn, cn, b_o, out, nullptr, nullptr);
}